// round 1
// baseline (speedup 1.0000x reference)
#include <cuda_runtime.h>
#include <cstdint>

#define BB 4
#define NN 8192
#define MM 8192
// block: 16(tx) x 8(ty) = 128 threads
// n-tile per block: 128  (n = nbase + i*16 + tx, i<8)
// m processed in tiles of 64 per iteration (m = mt + j*8 + ty, j<8)
// each block covers an M-chunk of 1024 -> 16 iterations
#define GRIDN (NN/128)     // 64
#define GRIDM 8            // M chunks of 1024
#define MCHUNK (MM/GRIDM)  // 1024

__device__ int g_d1min[BB*NN];
__device__ int g_d2min[BB*MM];

__global__ void init_kernel(float* out) {
    int idx = blockIdx.x * blockDim.x + threadIdx.x;
    if (idx < BB*NN) g_d1min[idx] = 0x7F7FFFFF;   // FLT_MAX bits
    if (idx < BB*MM) g_d2min[idx] = 0x7F7FFFFF;
    if (idx == 0) out[0] = 0.0f;
}

__global__ __launch_bounds__(128)
void chamfer_kernel(const float* __restrict__ p1, const float* __restrict__ p2) {
    const int tx = threadIdx.x & 15;
    const int ty = threadIdx.x >> 4;
    const int b  = blockIdx.z;
    const int nbase  = blockIdx.x * 128;
    const int mchunk = blockIdx.y * MCHUNK;

    __shared__ float4 shm[64];
    __shared__ float  dsh[64 * 17];   // reused for d2 tile reduce and d1 final reduce

    // Load this thread's 8 n-points; precompute negated coords + half-norm.
    float nx[8], ny[8], nz[8], hn[8], d1[8];
#pragma unroll
    for (int i = 0; i < 8; i++) {
        int n = nbase + i*16 + tx;
        const float* p = p1 + ((size_t)b * NN + n) * 3;
        float x = p[0], y = p[1], z = p[2];
        nx[i] = -x; ny[i] = -y; nz[i] = -z;
        hn[i] = 0.5f * (x*x + y*y + z*z);
        d1[i] = 3.0e38f;
    }

    for (int it = 0; it < MCHUNK/64; it++) {
        const int mt = mchunk + it * 64;
        __syncthreads();   // protect shm/dsh reuse from previous iteration readers
        if (threadIdx.x < 64) {
            int m = mt + threadIdx.x;
            const float* p = p2 + ((size_t)b * MM + m) * 3;
            float x = p[0], y = p[1], z = p[2];
            shm[threadIdx.x] = make_float4(x, y, z, 0.5f * (x*x + y*y + z*z));
        }
        __syncthreads();

        float d2p[8];
#pragma unroll
        for (int j = 0; j < 8; j++) {
            float4 q = shm[j*8 + ty];
            float dm = 3.0e38f;
#pragma unroll
            for (int i = 0; i < 8; i++) {
                // t = 0.5|a|^2 + 0.5|b|^2 - a.b ; squared dist = 2t
                float t = fmaf(nx[i], q.x, hn[i]);
                t = fmaf(ny[i], q.y, t);
                t = fmaf(nz[i], q.z, t);
                t = t + q.w;
                d1[i] = fminf(d1[i], t);
                dm    = fminf(dm, t);
            }
            d2p[j] = dm;
        }

        // reduce d2 partials across tx (16 threads per m)
#pragma unroll
        for (int j = 0; j < 8; j++) dsh[(ty*8 + j)*17 + tx] = d2p[j];
        __syncthreads();
        if (threadIdx.x < 64) {
            float v = dsh[threadIdx.x * 17];
#pragma unroll
            for (int k = 1; k < 16; k++) v = fminf(v, dsh[threadIdx.x*17 + k]);
            v = fmaxf(v, 0.0f);  // squared dist is >= 0 up to rounding; ref clamps
            atomicMin(&g_d2min[b*MM + mt + threadIdx.x], __float_as_int(v));
        }
    }

    // reduce d1 partials across ty (8 threads per n)
    __syncthreads();
#pragma unroll
    for (int i = 0; i < 8; i++) dsh[ty*136 + i*16 + tx] = d1[i];
    __syncthreads();
    {
        int nl = threadIdx.x;  // 0..127
        float v = dsh[nl];
#pragma unroll
        for (int k = 1; k < 8; k++) v = fminf(v, dsh[k*136 + nl]);
        v = fmaxf(v, 0.0f);
        atomicMin(&g_d1min[b*NN + nbase + nl], __float_as_int(v));
    }
}

__global__ void reduce_kernel(float* out) {
    const int total = BB*NN + BB*MM;  // 65536
    float v = 0.0f;
    for (int idx = blockIdx.x * blockDim.x + threadIdx.x; idx < total;
         idx += gridDim.x * blockDim.x) {
        int bits = (idx < BB*NN) ? g_d1min[idx] : g_d2min[idx - BB*NN];
        v += __int_as_float(bits);   // clamped min of t; dist = 2t
    }
    // warp reduce
    for (int o = 16; o > 0; o >>= 1) v += __shfl_down_sync(0xffffffffu, v, o);
    __shared__ float ws[32];
    int lane = threadIdx.x & 31, wid = threadIdx.x >> 5;
    if (lane == 0) ws[wid] = v;
    __syncthreads();
    if (wid == 0) {
        int nw = (blockDim.x + 31) >> 5;
        v = (lane < nw) ? ws[lane] : 0.0f;
        for (int o = 16; o > 0; o >>= 1) v += __shfl_down_sync(0xffffffffu, v, o);
        if (lane == 0) {
            // mean(d1)+mean(d2) = (sum1+sum2)*2 / (B*N)  [N==M]
            atomicAdd(out, v * (2.0f / (float)(BB*NN)));
        }
    }
}

extern "C" void kernel_launch(void* const* d_in, const int* in_sizes, int n_in,
                              void* d_out, int out_size) {
    const float* p1 = (const float*)d_in[0];
    const float* p2 = (const float*)d_in[1];
    float* out = (float*)d_out;
    (void)in_sizes; (void)n_in; (void)out_size;

    init_kernel<<<(BB*NN + 255)/256, 256>>>(out);
    dim3 grid(GRIDN, GRIDM, BB);
    chamfer_kernel<<<grid, 128>>>(p1, p2);
    reduce_kernel<<<64, 256>>>(out);
}